// round 1
// baseline (speedup 1.0000x reference)
#include <cuda_runtime.h>
#include <cstdint>

#define NNODES 50000
#define DFEAT  512
#define DHID   1024
#define NCOLS  2048   // [u | v] per node

// Scratch: UV[node][0:1024] = x@W1_top, UV[node][1024:2048] = x@W1_bot
__device__ float g_uv[(size_t)NNODES * NCOLS];  // ~410 MB static scratch

#define BM 128
#define BN 128
#define BK 16
#define APAD 4

__global__ __launch_bounds__(256)
void gemm_uv_kernel(const float* __restrict__ X, const float* __restrict__ W1) {
    __shared__ float As[BK][BM + APAD];
    __shared__ float Bs[BK][BN];

    const int bm    = blockIdx.y;
    const int bn    = blockIdx.x;
    const int row0  = bm * BM;
    const int colg0 = bn * BN;                 // global col in [0,2048)
    const int half  = (colg0 >= DHID) ? 1 : 0; // which W1 slice
    const float* Wbase = W1 + (size_t)(half * DFEAT) * DHID;
    const int wcol0 = colg0 - half * DHID;

    const int tid = threadIdx.x;
    const int tx  = tid & 15;   // 16 col-threads
    const int ty  = tid >> 4;   // 16 row-threads

    float acc[8][8];
#pragma unroll
    for (int i = 0; i < 8; i++)
#pragma unroll
        for (int j = 0; j < 8; j++) acc[i][j] = 0.f;

    for (int k0 = 0; k0 < DFEAT; k0 += BK) {
        // --- load A tile (BM x BK) transposed into As[k][m]; 512 float4, 2/thread
#pragma unroll
        for (int l = 0; l < 2; l++) {
            int i   = tid + l * 256;
            int ar  = i >> 2;       // 0..127
            int ac4 = i & 3;        // 0..3  (float4 along K)
            float4 v = make_float4(0.f, 0.f, 0.f, 0.f);
            if (row0 + ar < NNODES)
                v = *(const float4*)(X + (size_t)(row0 + ar) * DFEAT + k0 + ac4 * 4);
            As[ac4 * 4 + 0][ar] = v.x;
            As[ac4 * 4 + 1][ar] = v.y;
            As[ac4 * 4 + 2][ar] = v.z;
            As[ac4 * 4 + 3][ar] = v.w;
        }
        // --- load B tile (BK x BN); 512 float4, 2/thread (W1 is [512|512 x 1024] row-major)
#pragma unroll
        for (int l = 0; l < 2; l++) {
            int i   = tid + l * 256;
            int br  = i >> 5;       // 0..15
            int bc4 = i & 31;       // 0..31
            float4 v = *(const float4*)(Wbase + (size_t)(k0 + br) * DHID + wcol0 + bc4 * 4);
            *(float4*)(&Bs[br][bc4 * 4]) = v;
        }
        __syncthreads();

#pragma unroll
        for (int k = 0; k < BK; k++) {
            float ra[8], rb[8];
            float4 a0 = *(const float4*)(&As[k][ty * 8]);
            float4 a1 = *(const float4*)(&As[k][ty * 8 + 4]);
            ra[0] = a0.x; ra[1] = a0.y; ra[2] = a0.z; ra[3] = a0.w;
            ra[4] = a1.x; ra[5] = a1.y; ra[6] = a1.z; ra[7] = a1.w;
            float4 b0 = *(const float4*)(&Bs[k][tx * 8]);
            float4 b1v = *(const float4*)(&Bs[k][tx * 8 + 4]);
            rb[0] = b0.x; rb[1] = b0.y; rb[2] = b0.z; rb[3] = b0.w;
            rb[4] = b1v.x; rb[5] = b1v.y; rb[6] = b1v.z; rb[7] = b1v.w;
#pragma unroll
            for (int i = 0; i < 8; i++)
#pragma unroll
                for (int j = 0; j < 8; j++)
                    acc[i][j] = fmaf(ra[i], rb[j], acc[i][j]);
        }
        __syncthreads();
    }

#pragma unroll
    for (int i = 0; i < 8; i++) {
        int r = row0 + ty * 8 + i;
        if (r < NNODES) {
            float* dst = g_uv + (size_t)r * NCOLS + colg0 + tx * 8;
            *(float4*)(dst)     = make_float4(acc[i][0], acc[i][1], acc[i][2], acc[i][3]);
            *(float4*)(dst + 4) = make_float4(acc[i][4], acc[i][5], acc[i][6], acc[i][7]);
        }
    }
}

// Per-edge: out[e] = relu(u[src] + v[dst] + b1) . W2 + b2
// One block (256 threads) per edge; each thread handles 4 hidden dims (float4).
__global__ __launch_bounds__(256)
void edge_kernel(const void* __restrict__ srcp, const void* __restrict__ dstp,
                 const float* __restrict__ b1, const float* __restrict__ W2,
                 const float* __restrict__ b2, float* __restrict__ out, int E) {
    __shared__ int s_is64;
    __shared__ float warp_s[8];
    const int t = threadIdx.x;
    const int e = blockIdx.x;

    if (t == 0) {
        // dtype sniff: int64 little-endian values < 50000 => all odd 32-bit words are 0.
        const int* ps = (const int*)srcp;
        const int* pd = (const int*)dstp;
        int orv = 0;
#pragma unroll
        for (int i = 1; i < 16; i += 2) orv |= ps[i] | pd[i];
        s_is64 = (orv == 0) ? 1 : 0;
    }
    __syncthreads();

    long long s, d;
    if (s_is64) {
        s = ((const long long*)srcp)[e];
        d = ((const long long*)dstp)[e];
    } else {
        s = (long long)((const int*)srcp)[e];
        d = (long long)((const int*)dstp)[e];
    }

    const float4* u4 = (const float4*)(g_uv + (size_t)s * NCOLS);
    const float4* v4 = (const float4*)(g_uv + (size_t)d * NCOLS + DHID);
    float4 u  = u4[t];
    float4 v  = v4[t];
    float4 bb = ((const float4*)b1)[t];
    float4 w  = ((const float4*)W2)[t];

    float acc = fmaxf(u.x + v.x + bb.x, 0.f) * w.x
              + fmaxf(u.y + v.y + bb.y, 0.f) * w.y
              + fmaxf(u.z + v.z + bb.z, 0.f) * w.z
              + fmaxf(u.w + v.w + bb.w, 0.f) * w.w;

#pragma unroll
    for (int o = 16; o > 0; o >>= 1) acc += __shfl_xor_sync(0xffffffffu, acc, o);
    if ((t & 31) == 0) warp_s[t >> 5] = acc;
    __syncthreads();
    if (t < 8) {
        float a = warp_s[t];
#pragma unroll
        for (int o = 4; o > 0; o >>= 1) a += __shfl_xor_sync(0xffu, a, o);
        if (t == 0) out[e] = a + b2[0];
    }
}

extern "C" void kernel_launch(void* const* d_in, const int* in_sizes, int n_in,
                              void* d_out, int out_size) {
    const float* x   = (const float*)d_in[0];
    const void*  src = d_in[1];
    const void*  dst = d_in[2];
    const float* W1  = (const float*)d_in[3];
    const float* b1  = (const float*)d_in[4];
    const float* W2  = (const float*)d_in[5];
    const float* b2  = (const float*)d_in[6];
    float* out = (float*)d_out;
    const int E = in_sizes[1];

    dim3 ggrid(NCOLS / BN, (NNODES + BM - 1) / BM);   // (16, 391)
    gemm_uv_kernel<<<ggrid, 256>>>(x, W1);
    edge_kernel<<<E, 256>>>(src, dst, b1, W2, b2, out, E);
}

// round 3
// speedup vs baseline: 2.1644x; 2.1644x over previous
#include <cuda_runtime.h>
#include <cuda_bf16.h>
#include <cstdint>

#define NNODES 50000
#define DFEAT  512
#define DHID   1024
#define NCOLS  2048

// ---------------- device scratch ----------------
__device__ __align__(16) float g_uv[(size_t)NNODES * NCOLS];          // node GEMM output [N, 2048]
__device__ __align__(16) __nv_bfloat16 g_xhi[(size_t)NNODES * DFEAT];
__device__ __align__(16) __nv_bfloat16 g_xlo[(size_t)NNODES * DFEAT];
__device__ __align__(16) __nv_bfloat16 g_bhi[(size_t)NCOLS * DFEAT];  // W1^T hi [2048][512]
__device__ __align__(16) __nv_bfloat16 g_blo[(size_t)NCOLS * DFEAT];

__device__ __forceinline__ uint32_t smem_u32(const void* p) {
    uint32_t a;
    asm("{ .reg .u64 t; cvta.to.shared.u64 t, %1; cvt.u32.u64 %0, t; }" : "=r"(a) : "l"(p));
    return a;
}

#define LDSM_X4(r0, r1, r2, r3, a) \
    asm volatile("ldmatrix.sync.aligned.m8n8.x4.shared.b16 {%0,%1,%2,%3}, [%4];" \
                 : "=r"(r0), "=r"(r1), "=r"(r2), "=r"(r3) : "r"(a))

#define MMA_BF16(d, a, b) \
    asm volatile("mma.sync.aligned.m16n8k16.row.col.f32.bf16.bf16.f32 " \
                 "{%0,%1,%2,%3}, {%4,%5,%6,%7}, {%8,%9}, {%0,%1,%2,%3};" \
                 : "+f"((d)[0]), "+f"((d)[1]), "+f"((d)[2]), "+f"((d)[3]) \
                 : "r"((a)[0]), "r"((a)[1]), "r"((a)[2]), "r"((a)[3]), "r"((b)[0]), "r"((b)[1]))

#define CP_ASYNC16(sa, ga, sz) \
    asm volatile("cp.async.cg.shared.global [%0], [%1], 16, %2;" :: "r"(sa), "l"(ga), "r"(sz))
#define CP_COMMIT() asm volatile("cp.async.commit_group;" ::: "memory")
#define CP_WAIT(n)  asm volatile("cp.async.wait_group %0;" :: "n"(n) : "memory")

// ---------------- fp32 -> bf16 hi/lo split ----------------
__device__ __forceinline__ void split_bf16(float x, unsigned short& hi, unsigned short& lo) {
    __nv_bfloat16 h = __float2bfloat16(x);
    __nv_bfloat16 l = __float2bfloat16(x - __bfloat162float(h));
    hi = __bfloat16_as_ushort(h);
    lo = __bfloat16_as_ushort(l);
}

__global__ __launch_bounds__(256)
void convert_x_kernel(const float* __restrict__ X) {
    size_t i = (size_t)blockIdx.x * blockDim.x + threadIdx.x;   // float4 index
    const size_t n4 = (size_t)NNODES * DFEAT / 4;
    if (i >= n4) return;
    float4 v = ((const float4*)X)[i];
    unsigned short h0, h1, h2, h3, l0, l1, l2, l3;
    split_bf16(v.x, h0, l0); split_bf16(v.y, h1, l1);
    split_bf16(v.z, h2, l2); split_bf16(v.w, h3, l3);
    uint2 wh = make_uint2((uint32_t)h0 | ((uint32_t)h1 << 16), (uint32_t)h2 | ((uint32_t)h3 << 16));
    uint2 wl = make_uint2((uint32_t)l0 | ((uint32_t)l1 << 16), (uint32_t)l2 | ((uint32_t)l3 << 16));
    *(uint2*)(g_xhi + i * 4) = wh;
    *(uint2*)(g_xlo + i * 4) = wl;
}

__global__ __launch_bounds__(256)
void convert_w_kernel(const float* __restrict__ W1) {
    __shared__ float tile[32][33];
    const int k0 = blockIdx.x * 32;     // k in [0,512)
    const int n0 = blockIdx.y * 32;     // n in [0,2048)
    const int tx = threadIdx.x, ty = threadIdx.y;   // 32 x 8
    const int roff = (n0 >= DHID) ? DFEAT : 0;
#pragma unroll
    for (int j = 0; j < 32; j += 8) {
        int k = k0 + ty + j;
        int n = n0 + tx;
        tile[ty + j][tx] = W1[(size_t)(roff + k) * DHID + (n & (DHID - 1))];
    }
    __syncthreads();
#pragma unroll
    for (int j = 0; j < 32; j += 8) {
        int n = n0 + ty + j;
        int k = k0 + tx;
        unsigned short hi, lo;
        split_bf16(tile[tx][ty + j], hi, lo);
        g_bhi[(size_t)n * DFEAT + k] = __ushort_as_bfloat16(hi);
        g_blo[(size_t)n * DFEAT + k] = __ushort_as_bfloat16(lo);
    }
}

// ---------------- HMMA split-bf16 GEMM: g_uv = X @ [W1_top | W1_bot] ----------------
#define BM 128
#define BN 128
#define BK 32
#define PITCH 80                        // 5 x 16B: conflict-free ldmatrix, no swizzle
#define TILE_B (128 * PITCH)            // 10240 B
#define STAGE_B (4 * TILE_B)            // Ahi, Alo, Bhi, Blo = 40960 B
#define SMEM_DYN (2 * STAGE_B)          // 81920 B double-buffered

__global__ __launch_bounds__(256)
void gemm_mma_kernel() {
    extern __shared__ char smem[];
    const uint32_t sbase = smem_u32(smem);
    const int tid = threadIdx.x;
    const int wid = tid >> 5, lane = tid & 31;
    const int col0 = blockIdx.x * BN;
    const int row0 = blockIdx.y * BM;
    const int warp_m = wid & 3;         // 4 m-warps of 32 rows
    const int warp_n = wid >> 2;        // 2 n-warps of 64 cols

    float acc[2][8][4];
#pragma unroll
    for (int mi = 0; mi < 2; mi++)
#pragma unroll
        for (int ni = 0; ni < 8; ni++)
#pragma unroll
            for (int q = 0; q < 4; q++) acc[mi][ni][q] = 0.f;

    // --- stage fill: 4 tiles x 512 16B-chunks, 8 chunks/thread via cp.async
    const int lr = tid >> 2;            // row this thread fills (per 256-chunk pass covers rows lr, lr+64)
    const int lc4 = tid & 3;
    auto issue_stage = [&](int kt, int s) {
        const int k0 = kt * BK;
        const uint32_t sb = sbase + s * STAGE_B;
#pragma unroll
        for (int j = 0; j < 8; j++) {
            const int tile = j >> 1;
            const int r = lr + (j & 1) * 64;
            const uint32_t sa = sb + tile * TILE_B + r * PITCH + lc4 * 16;
            const __nv_bfloat16* g;
            int sz = 16;
            if (tile < 2) {
                g = (tile == 0 ? g_xhi : g_xlo) + (size_t)(row0 + r) * DFEAT + k0 + lc4 * 8;
                if (row0 + r >= NNODES) sz = 0;
            } else {
                g = (tile == 2 ? g_bhi : g_blo) + (size_t)(col0 + r) * DFEAT + k0 + lc4 * 8;
            }
            CP_ASYNC16(sa, g, sz);
        }
        CP_COMMIT();
    };

    // ldmatrix source addresses (stage-relative)
    const uint32_t a_off = (uint32_t)((warp_m * 32 + (lane & 15)) * PITCH + (lane >> 4) * 16);
    const int grp = lane >> 3, r8 = lane & 7;
    const uint32_t b_off = (uint32_t)((warp_n * 64 + ((grp & 2) ? 8 : 0) + r8) * PITCH
                                      + ((grp & 1) ? 16 : 0));

    issue_stage(0, 0);

    const int KT = DFEAT / BK;          // 16
    for (int kt = 0; kt < KT; kt++) {
        const int cur = kt & 1;
        if (kt + 1 < KT) { issue_stage(kt + 1, cur ^ 1); CP_WAIT(1); }
        else            { CP_WAIT(0); }
        __syncthreads();

        const uint32_t sb = sbase + cur * STAGE_B;
#pragma unroll
        for (int ks = 0; ks < 2; ks++) {
            const uint32_t kb = ks * 32;
            uint32_t ah[2][4], al[2][4], bh[8][2], bl[8][2];
#pragma unroll
            for (int mi = 0; mi < 2; mi++) {
                uint32_t aa = sb + a_off + mi * (16 * PITCH) + kb;
                LDSM_X4(ah[mi][0], ah[mi][1], ah[mi][2], ah[mi][3], aa);
                LDSM_X4(al[mi][0], al[mi][1], al[mi][2], al[mi][3], aa + TILE_B);
            }
#pragma unroll
            for (int p = 0; p < 4; p++) {           // each x4 covers 2 n-subtiles
                uint32_t ba = sb + 2 * TILE_B + b_off + p * (16 * PITCH) + kb;
                LDSM_X4(bh[2 * p][0], bh[2 * p][1], bh[2 * p + 1][0], bh[2 * p + 1][1], ba);
                LDSM_X4(bl[2 * p][0], bl[2 * p][1], bl[2 * p + 1][0], bl[2 * p + 1][1], ba + TILE_B);
            }
#pragma unroll
            for (int mi = 0; mi < 2; mi++)
#pragma unroll
                for (int ni = 0; ni < 8; ni++) {
                    MMA_BF16(acc[mi][ni], ah[mi], bh[ni]);
                    MMA_BF16(acc[mi][ni], ah[mi], bl[ni]);
                    MMA_BF16(acc[mi][ni], al[mi], bh[ni]);
                }
        }
        __syncthreads();
    }

    // --- epilogue
    const int r_lo = lane >> 2;
    const int c_lo = (lane & 3) * 2;
#pragma unroll
    for (int mi = 0; mi < 2; mi++) {
        const int row_a = row0 + warp_m * 32 + mi * 16 + r_lo;
        const int row_b = row_a + 8;
#pragma unroll
        for (int ni = 0; ni < 8; ni++) {
            const int col = col0 + warp_n * 64 + ni * 8 + c_lo;
            if (row_a < NNODES)
                *(float2*)(g_uv + (size_t)row_a * NCOLS + col) = make_float2(acc[mi][ni][0], acc[mi][ni][1]);
            if (row_b < NNODES)
                *(float2*)(g_uv + (size_t)row_b * NCOLS + col) = make_float2(acc[mi][ni][2], acc[mi][ni][3]);
        }
    }
}

// ---------------- per-edge: out[e] = relu(u[src] + v[dst] + b1) . W2 + b2 ----------------
__global__ __launch_bounds__(256)
void edge_kernel(const void* __restrict__ srcp, const void* __restrict__ dstp,
                 const float* __restrict__ b1, const float* __restrict__ W2,
                 const float* __restrict__ b2, float* __restrict__ out, int E) {
    __shared__ int s_is64;
    __shared__ float warp_s[8];
    const int t = threadIdx.x;
    const int e = blockIdx.x;

    if (t == 0) {
        const int* ps = (const int*)srcp;
        const int* pd = (const int*)dstp;
        int orv = 0;
#pragma unroll
        for (int i = 1; i < 16; i += 2) orv |= ps[i] | pd[i];
        s_is64 = (orv == 0) ? 1 : 0;
    }
    __syncthreads();

    long long s, d;
    if (s_is64) {
        s = ((const long long*)srcp)[e];
        d = ((const long long*)dstp)[e];
    } else {
        s = (long long)((const int*)srcp)[e];
        d = (long long)((const int*)dstp)[e];
    }

    const float4* u4 = (const float4*)(g_uv + (size_t)s * NCOLS);
    const float4* v4 = (const float4*)(g_uv + (size_t)d * NCOLS + DHID);
    float4 u  = u4[t];
    float4 v  = v4[t];
    float4 bb = ((const float4*)b1)[t];
    float4 w  = ((const float4*)W2)[t];

    float acc = fmaxf(u.x + v.x + bb.x, 0.f) * w.x
              + fmaxf(u.y + v.y + bb.y, 0.f) * w.y
              + fmaxf(u.z + v.z + bb.z, 0.f) * w.z
              + fmaxf(u.w + v.w + bb.w, 0.f) * w.w;

#pragma unroll
    for (int o = 16; o > 0; o >>= 1) acc += __shfl_xor_sync(0xffffffffu, acc, o);
    if ((t & 31) == 0) warp_s[t >> 5] = acc;
    __syncthreads();
    if (t < 8) {
        float a = warp_s[t];
#pragma unroll
        for (int o = 4; o > 0; o >>= 1) a += __shfl_xor_sync(0xffu, a, o);
        if (t == 0) out[e] = a + b2[0];
    }
}

extern "C" void kernel_launch(void* const* d_in, const int* in_sizes, int n_in,
                              void* d_out, int out_size) {
    const float* x   = (const float*)d_in[0];
    const void*  src = d_in[1];
    const void*  dst = d_in[2];
    const float* W1  = (const float*)d_in[3];
    const float* b1  = (const float*)d_in[4];
    const float* W2  = (const float*)d_in[5];
    const float* b2  = (const float*)d_in[6];
    float* out = (float*)d_out;
    const int E = in_sizes[1];

    cudaFuncSetAttribute(gemm_mma_kernel, cudaFuncAttributeMaxDynamicSharedMemorySize, SMEM_DYN);

    const size_t n4 = (size_t)NNODES * DFEAT / 4;
    convert_x_kernel<<<(unsigned)((n4 + 255) / 256), 256>>>(x);
    convert_w_kernel<<<dim3(DFEAT / 32, NCOLS / 32), dim3(32, 8)>>>(W1);
    gemm_mma_kernel<<<dim3(NCOLS / BN, (NNODES + BM - 1) / BM), 256, SMEM_DYN>>>();
    edge_kernel<<<E, 256>>>(src, dst, b1, W2, b2, out, E);
}